// round 11
// baseline (speedup 1.0000x reference)
#include <cuda_runtime.h>
#include <math.h>

#define BATCH 2
#define LDIM 3600
#define SDIM 3600
#define DDIM 256
#define LS 12960000
#define NP1 3601
#define CGROUPS 16
#define MU_CONST (1.0f/7200.0f)
#define INV_SCALE 1.52587890625e-4f  // 1/(256*256*0.1)

#define QSCALE 8128.0f               // 127 / 0.015625
#define QS (1.0f/8128.0f)
#define SKH_BLOCKS 148
#define SKH_THREADS 512
#define BGROUPS 36                   // 36 groups x 100 rows

static __device__ float    d_E[BATCH * LS];
static __device__ signed char d_E8[BATCH * LS];
static __device__ float    d_rinv[BATCH * LDIM];
static __device__ float    d_cinv[BATCH * SDIM];
static __device__ float    d_colpart[BATCH * CGROUPS * SDIM];
static __device__ unsigned d_rowmaxb[BATCH * LDIM];
static __device__ unsigned d_colmaxb[BATCH * SDIM];
static __device__ float    d_wu[BATCH * NP1];
static __device__ float    d_wv[BATCH * NP1];
static __device__ float    d_svpart[BATCH * BGROUPS * SDIM];
static __device__ float    d_swu_row[BATCH];
static __device__ float    d_swu_tot[BATCH];
static __device__ unsigned d_bar_count = 0;
static __device__ volatile unsigned d_bar_gen = 0;

__device__ __forceinline__ float warpSum(float v) {
#pragma unroll
    for (int o = 16; o > 0; o >>= 1) v += __shfl_down_sync(0xffffffffu, v, o);
    return v;
}
__device__ __forceinline__ float warpMax(float v) {
#pragma unroll
    for (int o = 16; o > 0; o >>= 1) v = fmaxf(v, __shfl_down_sync(0xffffffffu, v, o));
    return v;
}
__device__ __forceinline__ float blockSum256(float v, float* red) {
    int lane = threadIdx.x & 31, w = threadIdx.x >> 5;
    v = warpSum(v);
    if (lane == 0) red[w] = v;
    __syncthreads();
    float t = (threadIdx.x < 8) ? red[threadIdx.x] : 0.0f;
    if (w == 0) t = warpSum(t);
    return t;
}
// canonical cm expression; __fmul_rn blocks FMA contraction so all kernels
// recompute bit-identical values for the ==max comparisons.
__device__ __forceinline__ float cm_val(float e, float ri, float cj) {
    return __fmul_rn(__fmul_rn(__fmul_rn(e, e), ri), cj);
}

// ---- K1: fp32 SGEMM (128x128x16) + exp epilogue -> d_E (fp32) + d_E8 (int8 eps) ----
__global__ void __launch_bounds__(256, 2)
gemm_exp_kernel(const float* __restrict__ Q, const float* __restrict__ R) {
    const int b = blockIdx.z;
    const int row0 = blockIdx.y * 128, col0 = blockIdx.x * 128;
    __shared__ float As[16][132];
    __shared__ float Bs[16][132];
    const int tid = threadIdx.x, tx = tid & 15, ty = tid >> 4;
    float acc[8][8];
#pragma unroll
    for (int i = 0; i < 8; i++)
#pragma unroll
        for (int j = 0; j < 8; j++) acc[i][j] = 0.0f;

    const float* Qb = Q + (long)b * LDIM * DDIM;
    const float* Rb = R + (long)b * SDIM * DDIM;

    for (int kt = 0; kt < DDIM; kt += 16) {
#pragma unroll
        for (int l = 0; l < 2; l++) {
            int f = tid + l * 256;
            int r = f >> 2, c4 = (f & 3) << 2;
            float4 va = make_float4(0.f, 0.f, 0.f, 0.f);
            int ga = row0 + r;
            if (ga < LDIM) va = *(const float4*)(Qb + (long)ga * DDIM + kt + c4);
            As[c4 + 0][r] = va.x; As[c4 + 1][r] = va.y;
            As[c4 + 2][r] = va.z; As[c4 + 3][r] = va.w;
            float4 vb = make_float4(0.f, 0.f, 0.f, 0.f);
            int gb = col0 + r;
            if (gb < SDIM) vb = *(const float4*)(Rb + (long)gb * DDIM + kt + c4);
            Bs[c4 + 0][r] = vb.x; Bs[c4 + 1][r] = vb.y;
            Bs[c4 + 2][r] = vb.z; Bs[c4 + 3][r] = vb.w;
        }
        __syncthreads();
#pragma unroll
        for (int kk = 0; kk < 16; kk++) {
            float4 a0 = *(const float4*)&As[kk][ty * 8];
            float4 a1 = *(const float4*)&As[kk][ty * 8 + 4];
            float4 b0 = *(const float4*)&Bs[kk][tx * 8];
            float4 b1 = *(const float4*)&Bs[kk][tx * 8 + 4];
            float ra[8] = {a0.x, a0.y, a0.z, a0.w, a1.x, a1.y, a1.z, a1.w};
            float rb[8] = {b0.x, b0.y, b0.z, b0.w, b1.x, b1.y, b1.z, b1.w};
#pragma unroll
            for (int i = 0; i < 8; i++)
#pragma unroll
                for (int j = 0; j < 8; j++)
                    acc[i][j] = fmaf(ra[i], rb[j], acc[i][j]);
        }
        __syncthreads();
    }

    float* Eb = d_E + (long)b * LS;
    signed char* E8b = d_E8 + (long)b * LS;
    const int gi0 = row0 + ty * 8, gj0 = col0 + tx * 8;
#pragma unroll
    for (int i = 0; i < 8; i++) {
        int gi = gi0 + i;
        if (gi >= LDIM) break;
#pragma unroll
        for (int h = 0; h < 2; h++) {
            int gj = gj0 + h * 4;
            if (gj < SDIM) {
                float4 o;
                o.x = expf(acc[i][h * 4 + 0] * INV_SCALE);
                o.y = expf(acc[i][h * 4 + 1] * INV_SCALE);
                o.z = expf(acc[i][h * 4 + 2] * INV_SCALE);
                o.w = expf(acc[i][h * 4 + 3] * INV_SCALE);
                *(float4*)(Eb + (long)gi * SDIM + gj) = o;
                char4 qc;
                int q0 = __float2int_rn((o.x - 1.0f) * QSCALE);
                int q1 = __float2int_rn((o.y - 1.0f) * QSCALE);
                int q2 = __float2int_rn((o.z - 1.0f) * QSCALE);
                int q3 = __float2int_rn((o.w - 1.0f) * QSCALE);
                qc.x = (signed char)max(-127, min(127, q0));
                qc.y = (signed char)max(-127, min(127, q1));
                qc.z = (signed char)max(-127, min(127, q2));
                qc.w = (signed char)max(-127, min(127, q3));
                *(char4*)(E8b + (long)gi * SDIM + gj) = qc;
            }
        }
    }
}

// ---- K2a: row sums -> rinv ----
__global__ void rowsum_kernel() {  // grid (LDIM, BATCH), 256
    __shared__ float red[8];
    const int b = blockIdx.y, i = blockIdx.x;
    const float4* r4 = (const float4*)(d_E + (long)b * LS + (long)i * SDIM);
    float s = 0.0f;
    for (int f = threadIdx.x; f < 900; f += 256) {
        float4 v = r4[f];
        s += (v.x + v.y) + (v.z + v.w);
    }
    s = blockSum256(s, red);
    if (threadIdx.x == 0) d_rinv[b * LDIM + i] = 1.0f / s;
}

// ---- K2b: column sums, two-stage deterministic ----
__global__ void colsum_part_kernel() {  // grid (15, CGROUPS, BATCH)
    const int b = blockIdx.z, g = blockIdx.y;
    const int j = blockIdx.x * 256 + threadIdx.x;
    if (j >= SDIM) return;
    const float* p = d_E + (long)b * LS + (long)(g * 225) * SDIM + j;
    float s = 0.0f;
#pragma unroll 5
    for (int ii = 0; ii < 225; ii++) s += p[(long)ii * SDIM];
    d_colpart[(b * CGROUPS + g) * SDIM + j] = s;
}
__global__ void colsum_reduce_kernel() {  // grid 29 (also zeroes colmax bits)
    int idx = blockIdx.x * 256 + threadIdx.x;
    if (idx >= BATCH * SDIM) return;
    int b = idx / SDIM, j = idx - b * SDIM;
    float s = 0.0f;
#pragma unroll
    for (int g = 0; g < CGROUPS; g++) s += d_colpart[(b * CGROUPS + g) * SDIM + j];
    d_cinv[idx] = 1.0f / s;
    d_colmaxb[idx] = 0u;
}

// ---- K3a: cm -> out0 + per-row max bits ----
__global__ void cm_rowmax_kernel(float* __restrict__ out0) {  // grid (450, BATCH)
    __shared__ __align__(16) float s_ci[SDIM];
    const int b = blockIdx.y;
    for (int j = threadIdx.x; j < SDIM; j += 256) s_ci[j] = d_cinv[b * SDIM + j];
    __syncthreads();
    const int warp = threadIdx.x >> 5, lane = threadIdx.x & 31;
    const int i = blockIdx.x * 8 + warp;
    const float ri = d_rinv[b * LDIM + i];
    const float4* E4 = (const float4*)(d_E + (long)b * LS + (long)i * SDIM);
    const float4* C4 = (const float4*)s_ci;
    float4* O4 = (float4*)(out0 + (long)b * LS + (long)i * SDIM);
    float mx = 0.0f;
    for (int f = lane; f < 900; f += 32) {
        float4 e = E4[f], c = C4[f];
        float4 r;
        r.x = cm_val(e.x, ri, c.x); r.y = cm_val(e.y, ri, c.y);
        r.z = cm_val(e.z, ri, c.z); r.w = cm_val(e.w, ri, c.w);
        O4[f] = r;
        mx = fmaxf(mx, fmaxf(fmaxf(r.x, r.y), fmaxf(r.z, r.w)));
    }
    mx = warpMax(mx);
    if (lane == 0) d_rowmaxb[b * LDIM + i] = __float_as_uint(mx);
}

// ---- K3b: per-column max bits (cm>0 -> uint order == float order) ----
__global__ void colmax_kernel() {  // grid (15, CGROUPS, BATCH)
    __shared__ float s_ri[225];
    const int b = blockIdx.z, g = blockIdx.y;
    const int i0 = g * 225;
    if (threadIdx.x < 225) s_ri[threadIdx.x] = d_rinv[b * LDIM + i0 + threadIdx.x];
    __syncthreads();
    const int j = blockIdx.x * 256 + threadIdx.x;
    if (j >= SDIM) return;
    const float cj = d_cinv[b * SDIM + j];
    const float* p = d_E + (long)b * LS + (long)i0 * SDIM + j;
    float mx = 0.0f;
#pragma unroll 5
    for (int ii = 0; ii < 225; ii++)
        mx = fmaxf(mx, cm_val(p[(long)ii * SDIM], s_ri[ii], cj));
    atomicMax(&d_colmaxb[b * SDIM + j], __float_as_uint(mx));
}

// ---- K4: cf = cm * mutual ----
__global__ void cf_kernel(float* __restrict__ out1) {  // grid (450, BATCH)
    __shared__ __align__(16) float s_ci[SDIM];
    __shared__ unsigned s_cb[SDIM];
    const int b = blockIdx.y;
    for (int j = threadIdx.x; j < SDIM; j += 256) {
        s_ci[j] = d_cinv[b * SDIM + j];
        s_cb[j] = d_colmaxb[b * SDIM + j];
    }
    __syncthreads();
    const int warp = threadIdx.x >> 5, lane = threadIdx.x & 31;
    const int i = blockIdx.x * 8 + warp;
    const float ri = d_rinv[b * LDIM + i];
    const unsigned rb = d_rowmaxb[b * LDIM + i];
    const float* Er = d_E + (long)b * LS + (long)i * SDIM;
    float* o = out1 + (long)b * LS + (long)i * SDIM;
    for (int j = lane; j < SDIM; j += 32) {
        float cm = cm_val(Er[j], ri, s_ci[j]);
        unsigned cb = __float_as_uint(cm);
        o[j] = (cb == rb && cb == s_cb[j]) ? cm : 0.0f;
    }
}

// ---- grid barrier (all SKH_BLOCKS co-resident: 148 blocks, <=1 per SM) ----
__device__ __forceinline__ void grid_sync() {
    __syncthreads();
    if (threadIdx.x == 0) {
        __threadfence();  // release prior writes
        unsigned gen = d_bar_gen;
        if (atomicAdd(&d_bar_count, 1u) == SKH_BLOCKS - 1) {
            atomicExch(&d_bar_count, 0u);
            __threadfence();
            d_bar_gen = gen + 1;
        } else {
            while (d_bar_gen == gen) __nanosleep(64);
        }
        __threadfence();  // acquire
    }
    __syncthreads();
}

// ---- Persistent Sinkhorn: 50 iterations, int8 E, deterministic ----
__global__ void __launch_bounds__(SKH_THREADS)
sinkhorn_kernel(const float* __restrict__ alphap) {
    __shared__ __align__(16) float s_buf[7200];  // wv both batches (A) / wu chunk (B1)
    __shared__ float s_red[2][16];
    __shared__ float s_srow[2], s_wvn[2];
    const int tid = threadIdx.x, bid = blockIdx.x;
    const int wid = tid >> 5, lane = tid & 31;
    const float A = expf(alphap[0]);

    // init wv = 1 (fresh every launch -> deterministic)
    for (int idx = bid * SKH_THREADS + tid; idx < BATCH * NP1; idx += SKH_BLOCKS * SKH_THREADS)
        d_wv[idx] = 1.0f;
    grid_sync();

    for (int it = 0; it < 50; it++) {
        // ===== phase A: wu_i = MU/(S_wv + QS*sum(q*wv) + A*wv_n); wu_m analytic =====
        for (int k = tid; k < 7200; k += SKH_THREADS) {
            int b = k / 3600, j = k - b * 3600;
            s_buf[k] = d_wv[b * NP1 + j];
        }
        if (tid < 2) s_wvn[tid] = d_wv[tid * NP1 + SDIM];
        __syncthreads();
        {   // per-block deterministic S_wv per batch
            float s0 = 0.f, s1 = 0.f;
            for (int j = tid; j < 3600; j += SKH_THREADS) {
                s0 += s_buf[j]; s1 += s_buf[3600 + j];
            }
            s0 = warpSum(s0); s1 = warpSum(s1);
            if (lane == 0) { s_red[0][wid] = s0; s_red[1][wid] = s1; }
            __syncthreads();
            if (tid == 0) {
                float t0 = 0.f, t1 = 0.f;
#pragma unroll
                for (int w = 0; w < 16; w++) { t0 += s_red[0][w]; t1 += s_red[1][w]; }
                s_srow[0] = t0; s_srow[1] = t1;
            }
            __syncthreads();
        }
        int q = bid * 16 + wid;  // 4-row quad id, 1800 total
        if (q < 1800) {
            int b = q / 900;
            int i0 = (q - b * 900) * 4;
            const char4* base = (const char4*)(d_E8 + (long)b * LS + (long)i0 * SDIM);
            const float4* w4 = (const float4*)(s_buf + b * 3600);
            float t0 = 0.f, t1 = 0.f, t2 = 0.f, t3 = 0.f;
            for (int f = lane; f < 900; f += 32) {
                float4 w = w4[f];
                char4 c0 = base[f];
                char4 c1 = base[900 + f];
                char4 c2 = base[1800 + f];
                char4 c3 = base[2700 + f];
                t0 = fmaf((float)c0.x, w.x, fmaf((float)c0.y, w.y, fmaf((float)c0.z, w.z, fmaf((float)c0.w, w.w, t0))));
                t1 = fmaf((float)c1.x, w.x, fmaf((float)c1.y, w.y, fmaf((float)c1.z, w.z, fmaf((float)c1.w, w.w, t1))));
                t2 = fmaf((float)c2.x, w.x, fmaf((float)c2.y, w.y, fmaf((float)c2.z, w.z, fmaf((float)c2.w, w.w, t2))));
                t3 = fmaf((float)c3.x, w.x, fmaf((float)c3.y, w.y, fmaf((float)c3.z, w.z, fmaf((float)c3.w, w.w, t3))));
            }
            t0 = warpSum(t0); t1 = warpSum(t1); t2 = warpSum(t2); t3 = warpSum(t3);
            if (lane == 0) {
                float add = s_srow[b] + A * s_wvn[b];
                d_wu[b * NP1 + i0 + 0] = MU_CONST / (add + QS * t0);
                d_wu[b * NP1 + i0 + 1] = MU_CONST / (add + QS * t1);
                d_wu[b * NP1 + i0 + 2] = MU_CONST / (add + QS * t2);
                d_wu[b * NP1 + i0 + 3] = MU_CONST / (add + QS * t3);
            }
        }
        if (bid == SKH_BLOCKS - 1 && wid == 15 && lane < 2) {
            int b = lane;  // wu_m = 0.5/(A * sum_{j<=n} wv_j)
            d_wu[b * NP1 + LDIM] = 0.5f / (A * (s_srow[b] + s_wvn[b]));
        }
        grid_sync();

        // ===== phase B1: column partials of q^T @ wu; tasks = 2b x 36g x 2chunk =====
        if (bid < 144) {
            int b = bid / 72, rem = bid % 72;
            int g = rem >> 1, chunk = rem & 1;
            int i0 = g * 100;
            if (tid < 100) s_buf[tid] = d_wu[b * NP1 + i0 + tid];
            __syncthreads();
            if (tid < 450) {
                int j = chunk * 1800 + tid * 4;
                const char4* p = (const char4*)(d_E8 + (long)b * LS + (long)i0 * SDIM + j);
                float a0 = 0.f, a1 = 0.f, a2 = 0.f, a3 = 0.f;
#pragma unroll 4
                for (int i = 0; i < 100; i++) {
                    char4 c = p[(long)i * 900];
                    float u = s_buf[i];
                    a0 = fmaf((float)c.x, u, a0);
                    a1 = fmaf((float)c.y, u, a1);
                    a2 = fmaf((float)c.z, u, a2);
                    a3 = fmaf((float)c.w, u, a3);
                }
                *(float4*)&d_svpart[(b * BGROUPS + g) * SDIM + j] = make_float4(a0, a1, a2, a3);
            }
        } else if (bid == 144) {
            if (wid < 2) {  // S_wu per batch (deterministic warp reduction)
                int b = wid;
                float s = 0.f;
                for (int i = lane; i < LDIM; i += 32) s += d_wu[b * NP1 + i];
                s = warpSum(s);
                if (lane == 0) {
                    d_swu_row[b] = s;
                    d_swu_tot[b] = s + d_wu[b * NP1 + LDIM];
                }
            }
        }
        grid_sync();

        // ===== phase B2: wv_j = MU/(S_wu + QS*colsum + A*wu_m); wv_n analytic =====
        {
            int gidx = bid * SKH_THREADS + tid;
            if (gidx < 7200) {
                int b = gidx / 3600, j = gidx - b * 3600;
                float s = 0.f;
#pragma unroll
                for (int g = 0; g < BGROUPS; g++) s += d_svpart[(b * BGROUPS + g) * SDIM + j];
                float colsum = d_swu_row[b] + QS * s + A * d_wu[b * NP1 + LDIM];
                d_wv[b * NP1 + j] = MU_CONST / colsum;
            }
            if (gidx >= 7200 && gidx < 7202) {
                int b = gidx - 7200;
                d_wv[b * NP1 + SDIM] = 0.5f / (A * d_swu_tot[b]);
            }
        }
        grid_sync();
    }
}

// ---- Final: out2 = E * wu_i * wv_j * 7200 ----
__global__ void final_kernel(float* __restrict__ out2) {  // grid (450, BATCH)
    __shared__ __align__(16) float swv[SDIM];
    const int b = blockIdx.y;
    for (int j = threadIdx.x; j < SDIM; j += 256) swv[j] = d_wv[b * NP1 + j];
    __syncthreads();
    const int warp = threadIdx.x >> 5, lane = threadIdx.x & 31;
    const int i = blockIdx.x * 8 + warp;
    const float wu7200 = d_wu[b * NP1 + i] * 7200.0f;
    const float4* E4 = (const float4*)(d_E + (long)b * LS + (long)i * SDIM);
    const float4* W4 = (const float4*)swv;
    float4* O4 = (float4*)(out2 + (long)b * LS + (long)i * SDIM);
    for (int f = lane; f < 900; f += 32) {
        float4 e = E4[f], w = W4[f];
        float4 o;
        o.x = e.x * wu7200 * w.x; o.y = e.y * wu7200 * w.y;
        o.z = e.z * wu7200 * w.z; o.w = e.w * wu7200 * w.w;
        O4[f] = o;
    }
}

extern "C" void kernel_launch(void* const* d_in, const int* in_sizes, int n_in,
                              void* d_out, int out_size) {
    const float* Q = (const float*)d_in[0];
    const float* R = (const float*)d_in[1];
    const float* alpha = (const float*)d_in[2];
    float* out0 = (float*)d_out;
    float* out1 = out0 + (long)BATCH * LS;
    float* out2 = out1 + (long)BATCH * LS;

    gemm_exp_kernel<<<dim3(29, 29, BATCH), 256>>>(Q, R);
    rowsum_kernel<<<dim3(LDIM, BATCH), 256>>>();
    colsum_part_kernel<<<dim3(15, CGROUPS, BATCH), 256>>>();
    colsum_reduce_kernel<<<29, 256>>>();
    cm_rowmax_kernel<<<dim3(450, BATCH), 256>>>(out0);
    colmax_kernel<<<dim3(15, CGROUPS, BATCH), 256>>>();
    cf_kernel<<<dim3(450, BATCH), 256>>>(out1);
    sinkhorn_kernel<<<SKH_BLOCKS, SKH_THREADS>>>(alpha);
    final_kernel<<<dim3(450, BATCH), 256>>>(out2);
}

// round 12
// speedup vs baseline: 1.8450x; 1.8450x over previous
#include <cuda_runtime.h>
#include <math.h>

#define BATCH 2
#define LDIM 3600
#define SDIM 3600
#define DDIM 256
#define LS 12960000
#define NP1 3601
#define CGROUPS 16
#define MU_CONST (1.0f/7200.0f)
#define INV_SCALE 1.52587890625e-4f  // 1/(256*256*0.1)

#define QSCALE 8128.0f               // 127 / 0.015625
#define QS (1.0f/8128.0f)
#define SKH_BLOCKS 148
#define SKH_THREADS 1024

static __device__ float       d_E[BATCH * LS];
static __device__ signed char d_E8[BATCH * LS];
static __device__ signed char d_E8T[BATCH * LS];
static __device__ int         d_rowQ[BATCH * LDIM];
static __device__ int         d_colQ[BATCH * SDIM];
static __device__ float       d_rinv[BATCH * LDIM];
static __device__ float       d_cinv[BATCH * SDIM];
static __device__ float       d_colpart[BATCH * CGROUPS * SDIM];
static __device__ unsigned    d_rowmaxb[BATCH * LDIM];
static __device__ unsigned    d_colmaxb[BATCH * SDIM];
static __device__ float       d_wu[BATCH * NP1];
static __device__ float       d_wv[BATCH * NP1];
static __device__ unsigned    d_bar_count = 0;
static __device__ volatile unsigned d_bar_gen = 0;

__device__ __forceinline__ float warpSum(float v) {
#pragma unroll
    for (int o = 16; o > 0; o >>= 1) v += __shfl_down_sync(0xffffffffu, v, o);
    return v;
}
__device__ __forceinline__ float warpMax(float v) {
#pragma unroll
    for (int o = 16; o > 0; o >>= 1) v = fmaxf(v, __shfl_down_sync(0xffffffffu, v, o));
    return v;
}
__device__ __forceinline__ float blockSum256(float v, float* red) {
    int lane = threadIdx.x & 31, w = threadIdx.x >> 5;
    v = warpSum(v);
    if (lane == 0) red[w] = v;
    __syncthreads();
    float t = (threadIdx.x < 8) ? red[threadIdx.x] : 0.0f;
    if (w == 0) t = warpSum(t);
    return t;
}
// canonical cm expression; __fmul_rn blocks FMA contraction so all kernels
// recompute bit-identical values for the ==max comparisons.
__device__ __forceinline__ float cm_val(float e, float ri, float cj) {
    return __fmul_rn(__fmul_rn(__fmul_rn(e, e), ri), cj);
}

// ---- K1: fp32 SGEMM (128x128x16) + exp epilogue -> d_E (fp32) + d_E8 (int8 eps) ----
__global__ void __launch_bounds__(256, 2)
gemm_exp_kernel(const float* __restrict__ Q, const float* __restrict__ R) {
    const int b = blockIdx.z;
    const int row0 = blockIdx.y * 128, col0 = blockIdx.x * 128;
    __shared__ float As[16][132];
    __shared__ float Bs[16][132];
    const int tid = threadIdx.x, tx = tid & 15, ty = tid >> 4;
    float acc[8][8];
#pragma unroll
    for (int i = 0; i < 8; i++)
#pragma unroll
        for (int j = 0; j < 8; j++) acc[i][j] = 0.0f;

    const float* Qb = Q + (long)b * LDIM * DDIM;
    const float* Rb = R + (long)b * SDIM * DDIM;

    for (int kt = 0; kt < DDIM; kt += 16) {
#pragma unroll
        for (int l = 0; l < 2; l++) {
            int f = tid + l * 256;
            int r = f >> 2, c4 = (f & 3) << 2;
            float4 va = make_float4(0.f, 0.f, 0.f, 0.f);
            int ga = row0 + r;
            if (ga < LDIM) va = *(const float4*)(Qb + (long)ga * DDIM + kt + c4);
            As[c4 + 0][r] = va.x; As[c4 + 1][r] = va.y;
            As[c4 + 2][r] = va.z; As[c4 + 3][r] = va.w;
            float4 vb = make_float4(0.f, 0.f, 0.f, 0.f);
            int gb = col0 + r;
            if (gb < SDIM) vb = *(const float4*)(Rb + (long)gb * DDIM + kt + c4);
            Bs[c4 + 0][r] = vb.x; Bs[c4 + 1][r] = vb.y;
            Bs[c4 + 2][r] = vb.z; Bs[c4 + 3][r] = vb.w;
        }
        __syncthreads();
#pragma unroll
        for (int kk = 0; kk < 16; kk++) {
            float4 a0 = *(const float4*)&As[kk][ty * 8];
            float4 a1 = *(const float4*)&As[kk][ty * 8 + 4];
            float4 b0 = *(const float4*)&Bs[kk][tx * 8];
            float4 b1 = *(const float4*)&Bs[kk][tx * 8 + 4];
            float ra[8] = {a0.x, a0.y, a0.z, a0.w, a1.x, a1.y, a1.z, a1.w};
            float rb[8] = {b0.x, b0.y, b0.z, b0.w, b1.x, b1.y, b1.z, b1.w};
#pragma unroll
            for (int i = 0; i < 8; i++)
#pragma unroll
                for (int j = 0; j < 8; j++)
                    acc[i][j] = fmaf(ra[i], rb[j], acc[i][j]);
        }
        __syncthreads();
    }

    float* Eb = d_E + (long)b * LS;
    signed char* E8b = d_E8 + (long)b * LS;
    const int gi0 = row0 + ty * 8, gj0 = col0 + tx * 8;
#pragma unroll
    for (int i = 0; i < 8; i++) {
        int gi = gi0 + i;
        if (gi >= LDIM) break;
#pragma unroll
        for (int h = 0; h < 2; h++) {
            int gj = gj0 + h * 4;
            if (gj < SDIM) {
                float4 o;
                o.x = expf(acc[i][h * 4 + 0] * INV_SCALE);
                o.y = expf(acc[i][h * 4 + 1] * INV_SCALE);
                o.z = expf(acc[i][h * 4 + 2] * INV_SCALE);
                o.w = expf(acc[i][h * 4 + 3] * INV_SCALE);
                *(float4*)(Eb + (long)gi * SDIM + gj) = o;
                char4 qc;
                int q0 = __float2int_rn((o.x - 1.0f) * QSCALE);
                int q1 = __float2int_rn((o.y - 1.0f) * QSCALE);
                int q2 = __float2int_rn((o.z - 1.0f) * QSCALE);
                int q3 = __float2int_rn((o.w - 1.0f) * QSCALE);
                qc.x = (signed char)max(-127, min(127, q0));
                qc.y = (signed char)max(-127, min(127, q1));
                qc.z = (signed char)max(-127, min(127, q2));
                qc.w = (signed char)max(-127, min(127, q3));
                *(char4*)(E8b + (long)gi * SDIM + gj) = qc;
            }
        }
    }
}

// ---- transpose E8 -> E8T (100x100 byte tiles). grid (36, 36, BATCH), 256 thr ----
__global__ void transpose8_kernel() {
    __shared__ signed char t[100][104];
    const int b = blockIdx.z;
    const int i0 = blockIdx.x * 100, j0 = blockIdx.y * 100;
    const signed char* src = d_E8 + (long)b * LS;
    signed char* dst = d_E8T + (long)b * LS;
    for (int idx = threadIdx.x; idx < 2500; idx += 256) {
        int r = idx / 25, c = idx - r * 25;
        char4 v = *(const char4*)(src + (long)(i0 + r) * SDIM + j0 + c * 4);
        t[r][c * 4 + 0] = v.x; t[r][c * 4 + 1] = v.y;
        t[r][c * 4 + 2] = v.z; t[r][c * 4 + 3] = v.w;
    }
    __syncthreads();
    for (int idx = threadIdx.x; idx < 2500; idx += 256) {
        int jr = idx / 25, c = idx - jr * 25;
        int i4 = c * 4;
        char4 o;
        o.x = t[i4 + 0][jr]; o.y = t[i4 + 1][jr];
        o.z = t[i4 + 2][jr]; o.w = t[i4 + 3][jr];
        *(char4*)(dst + (long)(j0 + jr) * LDIM + i0 + i4) = o;
    }
}

// ---- per-row int8 sums via dp4a. which=0: E8->rowQ, which=1: E8T->colQ ----
__global__ void rowq_kernel(int which) {  // grid (450, BATCH), 256 thr (8 warps)
    const int b = blockIdx.y;
    const int wid = threadIdx.x >> 5, lane = threadIdx.x & 31;
    const int i = blockIdx.x * 8 + wid;
    const signed char* src = which ? d_E8T : d_E8;
    const int* row = (const int*)(src + (long)b * LS + (long)i * SDIM);
    int acc = 0;
#pragma unroll 4
    for (int f = lane; f < 896; f += 32) acc = __dp4a(row[f], 0x01010101, acc);
    if (lane < 4) acc = __dp4a(row[896 + lane], 0x01010101, acc);
    acc = __reduce_add_sync(0xffffffffu, acc);
    if (lane == 0) {
        if (which) d_colQ[b * SDIM + i] = acc;
        else       d_rowQ[b * LDIM + i] = acc;
    }
}

// ---- K2a: row sums -> rinv ----
__global__ void rowsum_kernel() {  // grid (LDIM, BATCH), 256
    __shared__ float red[8];
    const int b = blockIdx.y, i = blockIdx.x;
    const float4* r4 = (const float4*)(d_E + (long)b * LS + (long)i * SDIM);
    float s = 0.0f;
    for (int f = threadIdx.x; f < 900; f += 256) {
        float4 v = r4[f];
        s += (v.x + v.y) + (v.z + v.w);
    }
    s = blockSum256(s, red);
    if (threadIdx.x == 0) d_rinv[b * LDIM + i] = 1.0f / s;
}

// ---- K2b: column sums, two-stage deterministic ----
__global__ void colsum_part_kernel() {  // grid (15, CGROUPS, BATCH)
    const int b = blockIdx.z, g = blockIdx.y;
    const int j = blockIdx.x * 256 + threadIdx.x;
    if (j >= SDIM) return;
    const float* p = d_E + (long)b * LS + (long)(g * 225) * SDIM + j;
    float s = 0.0f;
#pragma unroll 5
    for (int ii = 0; ii < 225; ii++) s += p[(long)ii * SDIM];
    d_colpart[(b * CGROUPS + g) * SDIM + j] = s;
}
__global__ void colsum_reduce_kernel() {  // grid 29; also inits colmax bits + wv
    int idx = blockIdx.x * 256 + threadIdx.x;
    if (idx < BATCH * NP1) d_wv[idx] = 1.0f;
    if (idx >= BATCH * SDIM) return;
    int b = idx / SDIM, j = idx - b * SDIM;
    float s = 0.0f;
#pragma unroll
    for (int g = 0; g < CGROUPS; g++) s += d_colpart[(b * CGROUPS + g) * SDIM + j];
    d_cinv[idx] = 1.0f / s;
    d_colmaxb[idx] = 0u;
}

// ---- K3a: cm -> out0 + per-row max bits ----
__global__ void cm_rowmax_kernel(float* __restrict__ out0) {  // grid (450, BATCH)
    __shared__ __align__(16) float s_ci[SDIM];
    const int b = blockIdx.y;
    for (int j = threadIdx.x; j < SDIM; j += 256) s_ci[j] = d_cinv[b * SDIM + j];
    __syncthreads();
    const int warp = threadIdx.x >> 5, lane = threadIdx.x & 31;
    const int i = blockIdx.x * 8 + warp;
    const float ri = d_rinv[b * LDIM + i];
    const float4* E4 = (const float4*)(d_E + (long)b * LS + (long)i * SDIM);
    const float4* C4 = (const float4*)s_ci;
    float4* O4 = (float4*)(out0 + (long)b * LS + (long)i * SDIM);
    float mx = 0.0f;
    for (int f = lane; f < 900; f += 32) {
        float4 e = E4[f], c = C4[f];
        float4 r;
        r.x = cm_val(e.x, ri, c.x); r.y = cm_val(e.y, ri, c.y);
        r.z = cm_val(e.z, ri, c.z); r.w = cm_val(e.w, ri, c.w);
        O4[f] = r;
        mx = fmaxf(mx, fmaxf(fmaxf(r.x, r.y), fmaxf(r.z, r.w)));
    }
    mx = warpMax(mx);
    if (lane == 0) d_rowmaxb[b * LDIM + i] = __float_as_uint(mx);
}

// ---- K3b: per-column max bits (cm>0 -> uint order == float order) ----
__global__ void colmax_kernel() {  // grid (15, CGROUPS, BATCH)
    __shared__ float s_ri[225];
    const int b = blockIdx.z, g = blockIdx.y;
    const int i0 = g * 225;
    if (threadIdx.x < 225) s_ri[threadIdx.x] = d_rinv[b * LDIM + i0 + threadIdx.x];
    __syncthreads();
    const int j = blockIdx.x * 256 + threadIdx.x;
    if (j >= SDIM) return;
    const float cj = d_cinv[b * SDIM + j];
    const float* p = d_E + (long)b * LS + (long)i0 * SDIM + j;
    float mx = 0.0f;
#pragma unroll 5
    for (int ii = 0; ii < 225; ii++)
        mx = fmaxf(mx, cm_val(p[(long)ii * SDIM], s_ri[ii], cj));
    atomicMax(&d_colmaxb[b * SDIM + j], __float_as_uint(mx));
}

// ---- K4: cf = cm * mutual ----
__global__ void cf_kernel(float* __restrict__ out1) {  // grid (450, BATCH)
    __shared__ __align__(16) float s_ci[SDIM];
    __shared__ unsigned s_cb[SDIM];
    const int b = blockIdx.y;
    for (int j = threadIdx.x; j < SDIM; j += 256) {
        s_ci[j] = d_cinv[b * SDIM + j];
        s_cb[j] = d_colmaxb[b * SDIM + j];
    }
    __syncthreads();
    const int warp = threadIdx.x >> 5, lane = threadIdx.x & 31;
    const int i = blockIdx.x * 8 + warp;
    const float ri = d_rinv[b * LDIM + i];
    const unsigned rb = d_rowmaxb[b * LDIM + i];
    const float* Er = d_E + (long)b * LS + (long)i * SDIM;
    float* o = out1 + (long)b * LS + (long)i * SDIM;
    for (int j = lane; j < SDIM; j += 32) {
        float cm = cm_val(Er[j], ri, s_ci[j]);
        unsigned cb = __float_as_uint(cm);
        o[j] = (cb == rb && cb == s_cb[j]) ? cm : 0.0f;
    }
}

// ---- grid barrier (148 blocks, 1/SM, co-resident) ----
__device__ __forceinline__ void grid_sync() {
    __syncthreads();
    if (threadIdx.x == 0) {
        __threadfence();
        unsigned gen = d_bar_gen;
        if (atomicAdd(&d_bar_count, 1u) == SKH_BLOCKS - 1) {
            atomicExch(&d_bar_count, 0u);
            __threadfence();
            d_bar_gen = gen + 1;
        } else {
            while (d_bar_gen == gen) __nanosleep(64);
        }
        __threadfence();
    }
    __syncthreads();
}

// One Sinkhorn half-step over an int8 matrix M (row-major 3600x3600 per batch):
//   out_i = MU / (S_w + QS*(m*rsum_i + sv*dp4a(q_i, qw)) + A*bin_w)
// src = regular dual vector (3600/batch) read from gmem; bin handled analytically.
// Every block redundantly computes S, m, sv, packed qw -> bitwise identical.
__device__ __forceinline__ void sinkhorn_half(
    const signed char* __restrict__ M, const int* __restrict__ rsum,
    const float* __restrict__ srcvec, int src_bin_off,
    float* __restrict__ dstvec, int dst_bin_off, float A,
    float* s_w, int* s_q, float (*s_red)[32], float* s_S, float* s_m,
    float* s_sv, float* s_sinv, float* s_bin)
{
    const int tid = threadIdx.x, wid = tid >> 5, lane = tid & 31;
    // load regular entries of the dual vector (both batches)
    for (int k = tid; k < 7200; k += SKH_THREADS) {
        int b = (k >= 3600) ? 1 : 0;
        s_w[k] = srcvec[b * NP1 + (k - b * 3600)];
    }
    if (tid < 2) s_bin[tid] = srcvec[tid * NP1 + src_bin_off];
    __syncthreads();
    // sums (fixed order -> deterministic)
    {
        float s0 = 0.f, s1 = 0.f;
        for (int k = tid; k < 7200; k += SKH_THREADS) {
            float v = s_w[k];
            if (k < 3600) s0 += v; else s1 += v;
        }
        s0 = warpSum(s0); s1 = warpSum(s1);
        if (lane == 0) { s_red[0][wid] = s0; s_red[1][wid] = s1; }
        __syncthreads();
        if (tid == 0) {
            float t0 = 0.f, t1 = 0.f;
#pragma unroll
            for (int w = 0; w < 32; w++) { t0 += s_red[0][w]; t1 += s_red[1][w]; }
            s_S[0] = t0; s_S[1] = t1;
            s_m[0] = t0 * (1.0f / 3600.0f); s_m[1] = t1 * (1.0f / 3600.0f);
        }
        __syncthreads();
    }
    // max |dev| per batch
    {
        float m0 = s_m[0], m1 = s_m[1];
        float x0 = 0.f, x1 = 0.f;
        for (int k = tid; k < 7200; k += SKH_THREADS) {
            float d = s_w[k];
            if (k < 3600) x0 = fmaxf(x0, fabsf(d - m0));
            else          x1 = fmaxf(x1, fabsf(d - m1));
        }
        x0 = warpMax(x0); x1 = warpMax(x1);
        if (lane == 0) { s_red[0][wid] = x0; s_red[1][wid] = x1; }
        __syncthreads();
        if (tid == 0) {
#pragma unroll
            for (int w = 1; w < 32; w++) {
                s_red[0][0] = fmaxf(s_red[0][0], s_red[0][w]);
                s_red[1][0] = fmaxf(s_red[1][0], s_red[1][w]);
            }
            float mx0 = s_red[0][0], mx1 = s_red[1][0];
            s_sv[0] = mx0 * (1.0f / 127.0f);
            s_sv[1] = mx1 * (1.0f / 127.0f);
            s_sinv[0] = (mx0 > 0.f) ? 127.0f / mx0 : 0.0f;
            s_sinv[1] = (mx1 > 0.f) ? 127.0f / mx1 : 0.0f;
        }
        __syncthreads();
    }
    // quantize deviations -> packed int8
    {
        for (int p = tid; p < 1800; p += SKH_THREADS) {
            int b = (p >= 900) ? 1 : 0;
            int j0 = (p - b * 900) * 4;
            float m = s_m[b], sinv = s_sinv[b];
            const float* w = s_w + b * 3600 + j0;
            int q0 = max(-127, min(127, __float2int_rn((w[0] - m) * sinv)));
            int q1 = max(-127, min(127, __float2int_rn((w[1] - m) * sinv)));
            int q2 = max(-127, min(127, __float2int_rn((w[2] - m) * sinv)));
            int q3 = max(-127, min(127, __float2int_rn((w[3] - m) * sinv)));
            s_q[p] = (q0 & 0xFF) | ((q1 & 0xFF) << 8) | ((q2 & 0xFF) << 16) |
                     ((q3 & 0xFF) << 24);
        }
        __syncthreads();
    }
    // main: 3600 warp tasks, 2 rows each
    const int gwarp = blockIdx.x * (SKH_THREADS / 32) + wid;
    if (gwarp < 3600) {
        const int b = (gwarp >= 1800) ? 1 : 0;
        const int i0 = (gwarp - b * 1800) * 2;
        const int* row0 = (const int*)(M + (long)b * LS + (long)i0 * 3600);
        const int* row1 = row0 + 900;
        const int* qw = s_q + b * 900;
        int a0 = 0, a1 = 0;
#pragma unroll 4
        for (int f = lane; f < 896; f += 32) {
            int w = qw[f];
            a0 = __dp4a(row0[f], w, a0);
            a1 = __dp4a(row1[f], w, a1);
        }
        if (lane < 4) {
            int f = 896 + lane, w = qw[f];
            a0 = __dp4a(row0[f], w, a0);
            a1 = __dp4a(row1[f], w, a1);
        }
        a0 = __reduce_add_sync(0xffffffffu, a0);
        a1 = __reduce_add_sync(0xffffffffu, a1);
        if (lane == 0) {
            float base = s_S[b] + A * s_bin[b];
            float m = s_m[b], sv = s_sv[b];
            int r0 = rsum[b * 3600 + i0], r1 = rsum[b * 3600 + i0 + 1];
            dstvec[b * NP1 + i0]     = MU_CONST / (base + QS * (m * (float)r0 + sv * (float)a0));
            dstvec[b * NP1 + i0 + 1] = MU_CONST / (base + QS * (m * (float)r1 + sv * (float)a1));
        }
    }
    // bin entry of the destination vector
    if (blockIdx.x == SKH_BLOCKS - 1 && wid == (SKH_THREADS / 32) - 1 && lane < 2) {
        int b = lane;
        dstvec[b * NP1 + dst_bin_off] = 0.5f / (A * (s_S[b] + s_bin[b]));
    }
}

// ---- Persistent Sinkhorn: 50 iters, dp4a, deterministic ----
__global__ void __launch_bounds__(SKH_THREADS)
sinkhorn_kernel(const float* __restrict__ alphap) {
    __shared__ __align__(16) float s_w[7200];
    __shared__ int s_q[1800];
    __shared__ float s_red[2][32];
    __shared__ float s_S[2], s_m[2], s_sv[2], s_sinv[2], s_bin[2];
    const float A = expf(alphap[0]);
    // d_wv initialized to 1.0 by colsum_reduce_kernel earlier in the stream
    for (int it = 0; it < 50; it++) {
        // A: wu = f(E @ wv)
        sinkhorn_half(d_E8, d_rowQ, d_wv, SDIM, d_wu, LDIM, A,
                      s_w, s_q, s_red, s_S, s_m, s_sv, s_sinv, s_bin);
        grid_sync();
        // B: wv = f(E^T @ wu)
        sinkhorn_half(d_E8T, d_colQ, d_wu, LDIM, d_wv, SDIM, A,
                      s_w, s_q, s_red, s_S, s_m, s_sv, s_sinv, s_bin);
        grid_sync();
    }
}

// ---- Final: out2 = E * wu_i * wv_j * 7200 ----
__global__ void final_kernel(float* __restrict__ out2) {  // grid (450, BATCH)
    __shared__ __align__(16) float swv[SDIM];
    const int b = blockIdx.y;
    for (int j = threadIdx.x; j < SDIM; j += 256) swv[j] = d_wv[b * NP1 + j];
    __syncthreads();
    const int warp = threadIdx.x >> 5, lane = threadIdx.x & 31;
    const int i = blockIdx.x * 8 + warp;
    const float wu7200 = d_wu[b * NP1 + i] * 7200.0f;
    const float4* E4 = (const float4*)(d_E + (long)b * LS + (long)i * SDIM);
    const float4* W4 = (const float4*)swv;
    float4* O4 = (float4*)(out2 + (long)b * LS + (long)i * SDIM);
    for (int f = lane; f < 900; f += 32) {
        float4 e = E4[f], w = W4[f];
        float4 o;
        o.x = e.x * wu7200 * w.x; o.y = e.y * wu7200 * w.y;
        o.z = e.z * wu7200 * w.z; o.w = e.w * wu7200 * w.w;
        O4[f] = o;
    }
}

extern "C" void kernel_launch(void* const* d_in, const int* in_sizes, int n_in,
                              void* d_out, int out_size) {
    const float* Q = (const float*)d_in[0];
    const float* R = (const float*)d_in[1];
    const float* alpha = (const float*)d_in[2];
    float* out0 = (float*)d_out;
    float* out1 = out0 + (long)BATCH * LS;
    float* out2 = out1 + (long)BATCH * LS;

    gemm_exp_kernel<<<dim3(29, 29, BATCH), 256>>>(Q, R);
    transpose8_kernel<<<dim3(36, 36, BATCH), 256>>>();
    rowq_kernel<<<dim3(450, BATCH), 256>>>(0);
    rowq_kernel<<<dim3(450, BATCH), 256>>>(1);
    rowsum_kernel<<<dim3(LDIM, BATCH), 256>>>();
    colsum_part_kernel<<<dim3(15, CGROUPS, BATCH), 256>>>();
    colsum_reduce_kernel<<<29, 256>>>();
    cm_rowmax_kernel<<<dim3(450, BATCH), 256>>>(out0);
    colmax_kernel<<<dim3(15, CGROUPS, BATCH), 256>>>();
    cf_kernel<<<dim3(450, BATCH), 256>>>(out1);
    sinkhorn_kernel<<<SKH_BLOCKS, SKH_THREADS>>>(alpha);
    final_kernel<<<dim3(450, BATCH), 256>>>(out2);
}

// round 15
// speedup vs baseline: 2.0097x; 1.0892x over previous
#include <cuda_runtime.h>
#include <cuda_bf16.h>
#include <mma.h>
#include <math.h>

using namespace nvcuda;

#define BATCH 2
#define LDIM 3600
#define SDIM 3600
#define DDIM 256
#define LS 12960000
#define NP1 3601
#define CGROUPS 16
#define MU_CONST (1.0f/7200.0f)
#define INV_SCALE 1.52587890625e-4f  // 1/(256*256*0.1)

#define QSCALE 8128.0f               // 127 / 0.015625
#define QS (1.0f/8128.0f)
#define SKH_BLOCKS 148
#define SKH_THREADS 1024

#define MPAD 3712                     // 29*128, zero-padded rows for the GEMM

// GEMM smem layout (bytes)
#define AS_OFF 0
#define BS_OFF 10240
#define CS_OFF 20480
#define GSMEM_TOTAL (20480 + 128*132*4)   // 88064
#define TSTRIDE 40                         // bf16 elements per smem tile row
#define CSTRIDE 132

static __device__ float       d_E[BATCH * LS];
static __device__ signed char d_E8[BATCH * LS];
static __device__ signed char d_E8T[BATCH * LS];
static __device__ __nv_bfloat16 d_Qh[BATCH * MPAD * DDIM];
static __device__ __nv_bfloat16 d_Ql[BATCH * MPAD * DDIM];
static __device__ __nv_bfloat16 d_Rh[BATCH * MPAD * DDIM];
static __device__ __nv_bfloat16 d_Rl[BATCH * MPAD * DDIM];
static __device__ int         d_rowQ[BATCH * LDIM];
static __device__ int         d_colQ[BATCH * SDIM];
static __device__ float       d_rinv[BATCH * LDIM];
static __device__ float       d_cinv[BATCH * SDIM];
static __device__ float       d_colpart[BATCH * CGROUPS * SDIM];
static __device__ unsigned    d_rowmaxb[BATCH * LDIM];
static __device__ unsigned    d_colmaxb[BATCH * SDIM];
static __device__ float       d_wu[BATCH * NP1];
static __device__ float       d_wv[BATCH * NP1];
static __device__ unsigned    d_bar_count = 0;
static __device__ volatile unsigned d_bar_gen = 0;

__device__ __forceinline__ float warpSum(float v) {
#pragma unroll
    for (int o = 16; o > 0; o >>= 1) v += __shfl_down_sync(0xffffffffu, v, o);
    return v;
}
__device__ __forceinline__ float warpMax(float v) {
#pragma unroll
    for (int o = 16; o > 0; o >>= 1) v = fmaxf(v, __shfl_down_sync(0xffffffffu, v, o));
    return v;
}
__device__ __forceinline__ float blockSum256(float v, float* red) {
    int lane = threadIdx.x & 31, w = threadIdx.x >> 5;
    v = warpSum(v);
    if (lane == 0) red[w] = v;
    __syncthreads();
    float t = (threadIdx.x < 8) ? red[threadIdx.x] : 0.0f;
    if (w == 0) t = warpSum(t);
    return t;
}
// canonical cm expression; __fmul_rn blocks FMA contraction so all kernels
// recompute bit-identical values for the ==max comparisons.
__device__ __forceinline__ float cm_val(float e, float ri, float cj) {
    return __fmul_rn(__fmul_rn(__fmul_rn(e, e), ri), cj);
}

// ---- split fp32 -> (hi, lo) bf16 with zero row padding. grid (MPAD, BATCH), 256 ----
__global__ void split_kernel(const float* __restrict__ X,
                             __nv_bfloat16* __restrict__ H,
                             __nv_bfloat16* __restrict__ L) {
    int b = blockIdx.y, r = blockIdx.x, c = threadIdx.x;
    long dst = ((long)b * MPAD + r) * DDIM + c;
    float v = 0.0f;
    if (r < LDIM) v = X[((long)b * LDIM + r) * DDIM + c];
    __nv_bfloat16 h = __float2bfloat16(v);
    float lo = v - __bfloat162float(h);
    H[dst] = h;
    L[dst] = __float2bfloat16(lo);
}

// ---- wmma bf16 GEMM: D = Qh*Rh^T + Qh*Rl^T + Ql*Rh^T, fused exp -> d_E, d_E8 ----
// grid (29, 29, BATCH), 256 threads, dynamic smem GSMEM_TOTAL
__global__ void __launch_bounds__(256, 2)
gemm_wmma_kernel() {
    extern __shared__ char smem[];
    __nv_bfloat16* As = (__nv_bfloat16*)(smem + AS_OFF);
    __nv_bfloat16* Bs = (__nv_bfloat16*)(smem + BS_OFF);
    float* Cs = (float*)(smem + CS_OFF);

    const int tid = threadIdx.x, wid = tid >> 5;
    const int b = blockIdx.z;
    const int col0 = blockIdx.x * 128;   // R rows (N)
    const int row0 = blockIdx.y * 128;   // Q rows (M)
    const int wm = wid & 3, wn = wid >> 2;  // warp tile: 32 x 64

    const __nv_bfloat16* Qh = d_Qh + (long)b * MPAD * DDIM;
    const __nv_bfloat16* Ql = d_Ql + (long)b * MPAD * DDIM;
    const __nv_bfloat16* Rh = d_Rh + (long)b * MPAD * DDIM;
    const __nv_bfloat16* Rl = d_Rl + (long)b * MPAD * DDIM;
    const __nv_bfloat16* Ap[3] = {Qh, Qh, Ql};
    const __nv_bfloat16* Bp[3] = {Rh, Rl, Rh};

    wmma::fragment<wmma::accumulator, 16, 16, 16, float> acc[2][4];
#pragma unroll
    for (int i = 0; i < 2; i++)
#pragma unroll
        for (int j = 0; j < 4; j++) wmma::fill_fragment(acc[i][j], 0.0f);

    for (int p = 0; p < 3; p++) {
        const __nv_bfloat16* Ag = Ap[p];
        const __nv_bfloat16* Bg = Bp[p];
        for (int kc = 0; kc < DDIM; kc += 32) {
            __syncthreads();  // previous chunk's compute done before overwrite
#pragma unroll
            for (int t = 0; t < 2; t++) {
                int e = tid + t * 256;       // 512 16B-chunks per matrix
                int r = e >> 2, c8 = (e & 3) << 3;
                *(uint4*)&As[r * TSTRIDE + c8] =
                    *(const uint4*)(Ag + (long)(row0 + r) * DDIM + kc + c8);
                *(uint4*)&Bs[r * TSTRIDE + c8] =
                    *(const uint4*)(Bg + (long)(col0 + r) * DDIM + kc + c8);
            }
            __syncthreads();
#pragma unroll
            for (int kk = 0; kk < 32; kk += 16) {
                wmma::fragment<wmma::matrix_a, 16, 16, 16, __nv_bfloat16,
                               wmma::row_major> af[2];
                wmma::fragment<wmma::matrix_b, 16, 16, 16, __nv_bfloat16,
                               wmma::col_major> bf[4];
#pragma unroll
                for (int i = 0; i < 2; i++)
                    wmma::load_matrix_sync(af[i],
                        &As[(wm * 32 + i * 16) * TSTRIDE + kk], TSTRIDE);
#pragma unroll
                for (int j = 0; j < 4; j++)
                    wmma::load_matrix_sync(bf[j],
                        &Bs[(wn * 64 + j * 16) * TSTRIDE + kk], TSTRIDE);
#pragma unroll
                for (int i = 0; i < 2; i++)
#pragma unroll
                    for (int j = 0; j < 4; j++)
                        wmma::mma_sync(acc[i][j], af[i], bf[j], acc[i][j]);
            }
        }
    }
    __syncthreads();
#pragma unroll
    for (int i = 0; i < 2; i++)
#pragma unroll
        for (int j = 0; j < 4; j++)
            wmma::store_matrix_sync(
                &Cs[(wm * 32 + i * 16) * CSTRIDE + wn * 64 + j * 16],
                acc[i][j], CSTRIDE, wmma::mem_row_major);
    __syncthreads();

    // epilogue: exp + int8 quant, guarded writes
    float* Eb = d_E + (long)b * LS;
    signed char* E8b = d_E8 + (long)b * LS;
#pragma unroll
    for (int t = 0; t < 16; t++) {
        int e = tid + t * 256;              // 4096 float4 tasks
        int r = e >> 5, c4 = (e & 31) << 2;
        int gi = row0 + r, gj = col0 + c4;
        if (gi < LDIM && gj < SDIM) {
            const float* src = &Cs[r * CSTRIDE + c4];
            float4 o;
            o.x = expf(src[0] * INV_SCALE);
            o.y = expf(src[1] * INV_SCALE);
            o.z = expf(src[2] * INV_SCALE);
            o.w = expf(src[3] * INV_SCALE);
            *(float4*)(Eb + (long)gi * SDIM + gj) = o;
            char4 qc;
            qc.x = (signed char)max(-127, min(127, __float2int_rn((o.x - 1.0f) * QSCALE)));
            qc.y = (signed char)max(-127, min(127, __float2int_rn((o.y - 1.0f) * QSCALE)));
            qc.z = (signed char)max(-127, min(127, __float2int_rn((o.z - 1.0f) * QSCALE)));
            qc.w = (signed char)max(-127, min(127, __float2int_rn((o.w - 1.0f) * QSCALE)));
            *(char4*)(E8b + (long)gi * SDIM + gj) = qc;
        }
    }
}

// ---- transpose E8 -> E8T (100x100 byte tiles). grid (36, 36, BATCH), 256 thr ----
__global__ void transpose8_kernel() {
    __shared__ signed char t[100][104];
    const int b = blockIdx.z;
    const int i0 = blockIdx.x * 100, j0 = blockIdx.y * 100;
    const signed char* src = d_E8 + (long)b * LS;
    signed char* dst = d_E8T + (long)b * LS;
    for (int idx = threadIdx.x; idx < 2500; idx += 256) {
        int r = idx / 25, c = idx - r * 25;
        char4 v = *(const char4*)(src + (long)(i0 + r) * SDIM + j0 + c * 4);
        t[r][c * 4 + 0] = v.x; t[r][c * 4 + 1] = v.y;
        t[r][c * 4 + 2] = v.z; t[r][c * 4 + 3] = v.w;
    }
    __syncthreads();
    for (int idx = threadIdx.x; idx < 2500; idx += 256) {
        int jr = idx / 25, c = idx - jr * 25;
        int i4 = c * 4;
        char4 o;
        o.x = t[i4 + 0][jr]; o.y = t[i4 + 1][jr];
        o.z = t[i4 + 2][jr]; o.w = t[i4 + 3][jr];
        *(char4*)(dst + (long)(j0 + jr) * LDIM + i0 + i4) = o;
    }
}

// ---- per-row int8 sums via dp4a. which=0: E8->rowQ, which=1: E8T->colQ ----
__global__ void rowq_kernel(int which) {  // grid (450, BATCH), 256 thr
    const int b = blockIdx.y;
    const int wid = threadIdx.x >> 5, lane = threadIdx.x & 31;
    const int i = blockIdx.x * 8 + wid;
    const signed char* src = which ? d_E8T : d_E8;
    const int* row = (const int*)(src + (long)b * LS + (long)i * SDIM);
    int acc = 0;
#pragma unroll 4
    for (int f = lane; f < 896; f += 32) acc = __dp4a(row[f], 0x01010101, acc);
    if (lane < 4) acc = __dp4a(row[896 + lane], 0x01010101, acc);
    acc = __reduce_add_sync(0xffffffffu, acc);
    if (lane == 0) {
        if (which) d_colQ[b * SDIM + i] = acc;
        else       d_rowQ[b * LDIM + i] = acc;
    }
}

// ---- K2a: row sums -> rinv ----
__global__ void rowsum_kernel() {  // grid (LDIM, BATCH), 256
    __shared__ float red[8];
    const int b = blockIdx.y, i = blockIdx.x;
    const float4* r4 = (const float4*)(d_E + (long)b * LS + (long)i * SDIM);
    float s = 0.0f;
    for (int f = threadIdx.x; f < 900; f += 256) {
        float4 v = r4[f];
        s += (v.x + v.y) + (v.z + v.w);
    }
    s = blockSum256(s, red);
    if (threadIdx.x == 0) d_rinv[b * LDIM + i] = 1.0f / s;
}

// ---- K2b: column sums, two-stage deterministic ----
__global__ void colsum_part_kernel() {  // grid (15, CGROUPS, BATCH)
    const int b = blockIdx.z, g = blockIdx.y;
    const int j = blockIdx.x * 256 + threadIdx.x;
    if (j >= SDIM) return;
    const float* p = d_E + (long)b * LS + (long)(g * 225) * SDIM + j;
    float s = 0.0f;
#pragma unroll 5
    for (int ii = 0; ii < 225; ii++) s += p[(long)ii * SDIM];
    d_colpart[(b * CGROUPS + g) * SDIM + j] = s;
}
__global__ void colsum_reduce_kernel() {  // grid 29; also inits colmax bits + wv
    int idx = blockIdx.x * 256 + threadIdx.x;
    if (idx < BATCH * NP1) d_wv[idx] = 1.0f;
    if (idx >= BATCH * SDIM) return;
    int b = idx / SDIM, j = idx - b * SDIM;
    float s = 0.0f;
#pragma unroll
    for (int g = 0; g < CGROUPS; g++) s += d_colpart[(b * CGROUPS + g) * SDIM + j];
    d_cinv[idx] = 1.0f / s;
    d_colmaxb[idx] = 0u;
}

// ---- K3a: cm -> out0 + per-row max bits ----
__global__ void cm_rowmax_kernel(float* __restrict__ out0) {  // grid (450, BATCH)
    __shared__ __align__(16) float s_ci[SDIM];
    const int b = blockIdx.y;
    for (int j = threadIdx.x; j < SDIM; j += 256) s_ci[j] = d_cinv[b * SDIM + j];
    __syncthreads();
    const int warp = threadIdx.x >> 5, lane = threadIdx.x & 31;
    const int i = blockIdx.x * 8 + warp;
    const float ri = d_rinv[b * LDIM + i];
    const float4* E4 = (const float4*)(d_E + (long)b * LS + (long)i * SDIM);
    const float4* C4 = (const float4*)s_ci;
    float4* O4 = (float4*)(out0 + (long)b * LS + (long)i * SDIM);
    float mx = 0.0f;
    for (int f = lane; f < 900; f += 32) {
        float4 e = E4[f], c = C4[f];
        float4 r;
        r.x = cm_val(e.x, ri, c.x); r.y = cm_val(e.y, ri, c.y);
        r.z = cm_val(e.z, ri, c.z); r.w = cm_val(e.w, ri, c.w);
        O4[f] = r;
        mx = fmaxf(mx, fmaxf(fmaxf(r.x, r.y), fmaxf(r.z, r.w)));
    }
    mx = warpMax(mx);
    if (lane == 0) d_rowmaxb[b * LDIM + i] = __float_as_uint(mx);
}

// ---- K3b: per-column max bits (cm>0 -> uint order == float order) ----
__global__ void colmax_kernel() {  // grid (15, CGROUPS, BATCH)
    __shared__ float s_ri[225];
    const int b = blockIdx.z, g = blockIdx.y;
    const int i0 = g * 225;
    if (threadIdx.x < 225) s_ri[threadIdx.x] = d_rinv[b * LDIM + i0 + threadIdx.x];
    __syncthreads();
    const int j = blockIdx.x * 256 + threadIdx.x;
    if (j >= SDIM) return;
    const float cj = d_cinv[b * SDIM + j];
    const float* p = d_E + (long)b * LS + (long)i0 * SDIM + j;
    float mx = 0.0f;
#pragma unroll 5
    for (int ii = 0; ii < 225; ii++)
        mx = fmaxf(mx, cm_val(p[(long)ii * SDIM], s_ri[ii], cj));
    atomicMax(&d_colmaxb[b * SDIM + j], __float_as_uint(mx));
}

// ---- K4: cf = cm * mutual ----
__global__ void cf_kernel(float* __restrict__ out1) {  // grid (450, BATCH)
    __shared__ __align__(16) float s_ci[SDIM];
    __shared__ unsigned s_cb[SDIM];
    const int b = blockIdx.y;
    for (int j = threadIdx.x; j < SDIM; j += 256) {
        s_ci[j] = d_cinv[b * SDIM + j];
        s_cb[j] = d_colmaxb[b * SDIM + j];
    }
    __syncthreads();
    const int warp = threadIdx.x >> 5, lane = threadIdx.x & 31;
    const int i = blockIdx.x * 8 + warp;
    const float ri = d_rinv[b * LDIM + i];
    const unsigned rb = d_rowmaxb[b * LDIM + i];
    const float* Er = d_E + (long)b * LS + (long)i * SDIM;
    float* o = out1 + (long)b * LS + (long)i * SDIM;
    for (int j = lane; j < SDIM; j += 32) {
        float cm = cm_val(Er[j], ri, s_ci[j]);
        unsigned cb = __float_as_uint(cm);
        o[j] = (cb == rb && cb == s_cb[j]) ? cm : 0.0f;
    }
}

// ---- grid barrier (148 blocks, 1/SM, co-resident) ----
__device__ __forceinline__ void grid_sync() {
    __syncthreads();
    if (threadIdx.x == 0) {
        __threadfence();
        unsigned gen = d_bar_gen;
        if (atomicAdd(&d_bar_count, 1u) == SKH_BLOCKS - 1) {
            atomicExch(&d_bar_count, 0u);
            __threadfence();
            d_bar_gen = gen + 1;
        } else {
            while (d_bar_gen == gen) __nanosleep(64);
        }
        __threadfence();
    }
    __syncthreads();
}

// One Sinkhorn half-step over an int8 matrix M (row-major 3600x3600 per batch):
//   out_i = MU / (S_w + QS*(m*rsum_i + sv*dp4a(q_i, qw)) + A*bin_w)
__device__ __forceinline__ void sinkhorn_half(
    const signed char* __restrict__ M, const int* __restrict__ rsum,
    const float* __restrict__ srcvec, int src_bin_off,
    float* __restrict__ dstvec, int dst_bin_off, float A,
    float* s_w, int* s_q, float (*s_red)[32], float* s_S, float* s_m,
    float* s_sv, float* s_sinv, float* s_bin)
{
    const int tid = threadIdx.x, wid = tid >> 5, lane = tid & 31;
    for (int k = tid; k < 7200; k += SKH_THREADS) {
        int b = (k >= 3600) ? 1 : 0;
        s_w[k] = srcvec[b * NP1 + (k - b * 3600)];
    }
    if (tid < 2) s_bin[tid] = srcvec[tid * NP1 + src_bin_off];
    __syncthreads();
    {
        float s0 = 0.f, s1 = 0.f;
        for (int k = tid; k < 7200; k += SKH_THREADS) {
            float v = s_w[k];
            if (k < 3600) s0 += v; else s1 += v;
        }
        s0 = warpSum(s0); s1 = warpSum(s1);
        if (lane == 0) { s_red[0][wid] = s0; s_red[1][wid] = s1; }
        __syncthreads();
        if (tid == 0) {
            float t0 = 0.f, t1 = 0.f;
#pragma unroll
            for (int w = 0; w < 32; w++) { t0 += s_red[0][w]; t1 += s_red[1][w]; }
            s_S[0] = t0; s_S[1] = t1;
            s_m[0] = t0 * (1.0f / 3600.0f); s_m[1] = t1 * (1.0f / 3600.0f);
        }
        __syncthreads();
    }
    {
        float m0 = s_m[0], m1 = s_m[1];
        float x0 = 0.f, x1 = 0.f;
        for (int k = tid; k < 7200; k += SKH_THREADS) {
            float d = s_w[k];
            if (k < 3600) x0 = fmaxf(x0, fabsf(d - m0));
            else          x1 = fmaxf(x1, fabsf(d - m1));
        }
        x0 = warpMax(x0); x1 = warpMax(x1);
        if (lane == 0) { s_red[0][wid] = x0; s_red[1][wid] = x1; }
        __syncthreads();
        if (tid == 0) {
#pragma unroll
            for (int w = 1; w < 32; w++) {
                s_red[0][0] = fmaxf(s_red[0][0], s_red[0][w]);
                s_red[1][0] = fmaxf(s_red[1][0], s_red[1][w]);
            }
            float mx0 = s_red[0][0], mx1 = s_red[1][0];
            s_sv[0] = mx0 * (1.0f / 127.0f);
            s_sv[1] = mx1 * (1.0f / 127.0f);
            s_sinv[0] = (mx0 > 0.f) ? 127.0f / mx0 : 0.0f;
            s_sinv[1] = (mx1 > 0.f) ? 127.0f / mx1 : 0.0f;
        }
        __syncthreads();
    }
    {
        for (int p = tid; p < 1800; p += SKH_THREADS) {
            int b = (p >= 900) ? 1 : 0;
            int j0 = (p - b * 900) * 4;
            float m = s_m[b], sinv = s_sinv[b];
            const float* w = s_w + b * 3600 + j0;
            int q0 = max(-127, min(127, __float2int_rn((w[0] - m) * sinv)));
            int q1 = max(-127, min(127, __float2int_rn((w[1] - m) * sinv)));
            int q2 = max(-127, min(127, __float2int_rn((w[2] - m) * sinv)));
            int q3 = max(-127, min(127, __float2int_rn((w[3] - m) * sinv)));
            s_q[p] = (q0 & 0xFF) | ((q1 & 0xFF) << 8) | ((q2 & 0xFF) << 16) |
                     ((q3 & 0xFF) << 24);
        }
        __syncthreads();
    }
    const int gwarp = blockIdx.x * (SKH_THREADS / 32) + wid;
    if (gwarp < 3600) {
        const int b = (gwarp >= 1800) ? 1 : 0;
        const int i0 = (gwarp - b * 1800) * 2;
        const int* row0 = (const int*)(M + (long)b * LS + (long)i0 * 3600);
        const int* row1 = row0 + 900;
        const int* qw = s_q + b * 900;
        int a0 = 0, a1 = 0;
#pragma unroll 4
        for (int f = lane; f < 896; f += 32) {
            int w = qw[f];
            a0 = __dp4a(row0[f], w, a0);
            a1 = __dp4a(row1[f], w, a1);
        }
        if (lane < 4) {
            int f = 896 + lane, w = qw[f];
            a0 = __dp4a(row0[f], w, a0);
            a1 = __dp4a(row1[f], w, a1);
        }
        a0 = __reduce_add_sync(0xffffffffu, a0);
        a1 = __reduce_add_sync(0xffffffffu, a1);
        if (lane == 0) {
            float base = s_S[b] + A * s_bin[b];
            float m = s_m[b], sv = s_sv[b];
            int r0 = rsum[b * 3600 + i0], r1 = rsum[b * 3600 + i0 + 1];
            dstvec[b * NP1 + i0]     = MU_CONST / (base + QS * (m * (float)r0 + sv * (float)a0));
            dstvec[b * NP1 + i0 + 1] = MU_CONST / (base + QS * (m * (float)r1 + sv * (float)a1));
        }
    }
    if (blockIdx.x == SKH_BLOCKS - 1 && wid == (SKH_THREADS / 32) - 1 && lane < 2) {
        int b = lane;
        dstvec[b * NP1 + dst_bin_off] = 0.5f / (A * (s_S[b] + s_bin[b]));
    }
}

// ---- Persistent Sinkhorn: 50 iters, dp4a, deterministic ----
__global__ void __launch_bounds__(SKH_THREADS)
sinkhorn_kernel(const float* __restrict__ alphap) {
    __shared__ __align__(16) float s_w[7200];
    __shared__ int s_q[1800];
    __shared__ float s_red[2][32];
    __shared__ float s_S[2], s_m[2], s_sv[2], s_sinv[2], s_bin[2];
    const float A = expf(alphap[0]);
    for (int it = 0; it < 50; it++) {
        sinkhorn_half(d_E8, d_rowQ, d_wv, SDIM, d_wu, LDIM, A,
                      s_w, s_q, s_red, s_S, s_m, s_sv, s_sinv, s_bin);
        grid_sync();
        sinkhorn_half(d_E8T, d_colQ, d_wu, LDIM, d_wv, SDIM, A,
                      s_w, s_q, s_red, s_S, s_m, s_sv, s_sinv, s_bin);
        grid_sync();
    }
}

// ---- Final: out2 = E * wu_i * wv_j * 7200 ----
__global__ void final_kernel(float* __restrict__ out2) {  // grid (450, BATCH)
    __shared__ __align__(16) float swv[SDIM];
    const int b = blockIdx.y;
    for (int j = threadIdx.x; j < SDIM; j += 256) swv[j] = d_wv[b * NP1 + j];
    __syncthreads();
    const int warp = threadIdx.x >> 5, lane = threadIdx.x & 31;
    const int i = blockIdx.x * 8 + warp;
    const float wu7200 = d_wu[b * NP1 + i] * 7200.0f;
    const float4* E4 = (const float4*)(d_E + (long)b * LS + (long)i * SDIM);
    const float4* W4 = (const float4*)swv;
    float4* O4 = (float4*)(out2 + (long)b * LS + (long)i * SDIM);
    for (int f = lane; f < 900; f += 32) {
        float4 e = E4[f], w = W4[f];
        float4 o;
        o.x = e.x * wu7200 * w.x; o.y = e.y * wu7200 * w.y;
        o.z = e.z * wu7200 * w.z; o.w = e.w * wu7200 * w.w;
        O4[f] = o;
    }
}

extern "C" void kernel_launch(void* const* d_in, const int* in_sizes, int n_in,
                              void* d_out, int out_size) {
    const float* Q = (const float*)d_in[0];
    const float* R = (const float*)d_in[1];
    const float* alpha = (const float*)d_in[2];
    float* out0 = (float*)d_out;
    float* out1 = out0 + (long)BATCH * LS;
    float* out2 = out1 + (long)BATCH * LS;

    cudaFuncSetAttribute(gemm_wmma_kernel,
                         cudaFuncAttributeMaxDynamicSharedMemorySize,
                         GSMEM_TOTAL);

    __nv_bfloat16 *Qh, *Ql, *Rh, *Rl;
    cudaGetSymbolAddress((void**)&Qh, d_Qh);
    cudaGetSymbolAddress((void**)&Ql, d_Ql);
    cudaGetSymbolAddress((void**)&Rh, d_Rh);
    cudaGetSymbolAddress((void**)&Rl, d_Rl);

    split_kernel<<<dim3(MPAD, BATCH), 256>>>(Q, Qh, Ql);
    split_kernel<<<dim3(MPAD, BATCH), 256>>>(R, Rh, Rl);
    gemm_wmma_kernel<<<dim3(29, 29, BATCH), 256, GSMEM_TOTAL>>>();
    transpose8_kernel<<<dim3(36, 36, BATCH), 256>>>();
    rowq_kernel<<<dim3(450, BATCH), 256>>>(0);
    rowq_kernel<<<dim3(450, BATCH), 256>>>(1);
    rowsum_kernel<<<dim3(LDIM, BATCH), 256>>>();
    colsum_part_kernel<<<dim3(15, CGROUPS, BATCH), 256>>>();
    colsum_reduce_kernel<<<29, 256>>>();
    cm_rowmax_kernel<<<dim3(450, BATCH), 256>>>(out0);
    colmax_kernel<<<dim3(15, CGROUPS, BATCH), 256>>>();
    cf_kernel<<<dim3(450, BATCH), 256>>>(out1);
    sinkhorn_kernel<<<SKH_BLOCKS, SKH_THREADS>>>(alpha);
    final_kernel<<<dim3(450, BATCH), 256>>>(out2);
}